// round 1
// baseline (speedup 1.0000x reference)
#include <cuda_runtime.h>
#include <cstdint>

#define BB 64
#define TT 512
#define EE 256
#define H4 1024
#define KK 9

// ---------------- device scratch (static, zero-init) ----------------
__device__ float g_wt[4][EE * H4];          // transposed weights [k][j]: 0=ih_f 1=ih_b 2=hh_f 3=hh_b
__device__ float g_xp[2 * TT * BB * H4];    // [dir][step][b][j]  (256 MB)
__device__ float g_seq[(size_t)BB * TT * 512]; // [b][t][2H]
__device__ float g_gates[2][BB * H4];
__device__ float g_h[2][BB * EE];
__device__ float g_c[2][BB * EE];
__device__ float g_logits[BB * TT * KK];
__device__ float g_llh[BB];
__device__ int   g_bar_count[2];
__device__ int   g_bar_gen[2];

__device__ __forceinline__ float sigmoidf_(float x) { return 1.0f / (1.0f + expf(-x)); }

// ---------------- per-direction grid barrier (64 CTAs, co-resident) ----------------
__device__ __forceinline__ void grid_bar(int dir, int n) {
    __syncthreads();
    if (threadIdx.x == 0) {
        int gen = ((volatile int*)g_bar_gen)[dir];
        __threadfence();
        int t = atomicAdd(&g_bar_count[dir], 1);
        if (t == n - 1) {
            g_bar_count[dir] = 0;
            __threadfence();
            atomicAdd(&g_bar_gen[dir], 1);
        } else {
            while (((volatile int*)g_bar_gen)[dir] == gen) { __nanosleep(64); }
            __threadfence();
        }
    }
    __syncthreads();
}

// ---------------- kernel 1: transpose the 4 weight matrices [1024,256] -> [256,1024] ----------------
__global__ void transpose_w_kernel(const float* __restrict__ wf, const float* __restrict__ wb,
                                   const float* __restrict__ whf, const float* __restrict__ whb) {
    int idx = blockIdx.x * 256 + threadIdx.x;      // 4 * 262144 total
    int srcid = idx >> 18;
    int m = idx & 262143;
    int k = m >> 10;
    int j = m & 1023;
    const float* src = (srcid == 0) ? wf : (srcid == 1) ? wb : (srcid == 2) ? whf : whb;
    g_wt[srcid][k * H4 + j] = src[j * EE + k];
}

// ---------------- kernel 2: embedding gather + input projections ----------------
// grid (2048 token-tiles, 8 j-tiles, 2 dirs), 256 threads
__global__ void proj_kernel(const int* __restrict__ word_ids, const float* __restrict__ embed,
                            const float* __restrict__ b_f, const float* __restrict__ b_b) {
    __shared__ float es[16][EE];
    __shared__ int wids[16];

    int dir = blockIdx.z;
    int jt  = blockIdx.y;
    int tile = blockIdx.x;
    int s  = tile >> 2;
    int b0 = (tile & 3) * 16;
    int t_src = dir ? (TT - 1 - s) : s;
    int tid = threadIdx.x;

    if (tid < 16) wids[tid] = word_ids[(b0 + tid) * TT + t_src];
    __syncthreads();
    // load 16 embedding rows (16*256 floats = 1024 float4)
    for (int i = tid; i < 1024; i += 256) {
        int r = i >> 6, c = i & 63;
        ((float4*)es[r])[c] = ((const float4*)(embed + (size_t)wids[r] * EE))[c];
    }
    __syncthreads();

    int jl = tid & 127;
    int th = tid >> 7;          // 0/1 -> token rows th*8 .. th*8+7
    int j  = jt * 128 + jl;
    const float* __restrict__ wt = g_wt[dir];   // transposed w_ih

    float acc[8];
#pragma unroll
    for (int r = 0; r < 8; r++) acc[r] = 0.0f;

#pragma unroll 4
    for (int k = 0; k < EE; k += 4) {
        float w0 = wt[(k + 0) * H4 + j];
        float w1 = wt[(k + 1) * H4 + j];
        float w2 = wt[(k + 2) * H4 + j];
        float w3 = wt[(k + 3) * H4 + j];
#pragma unroll
        for (int r = 0; r < 8; r++) {
            float4 h4 = *(const float4*)&es[th * 8 + r][k];
            acc[r] += w0 * h4.x + w1 * h4.y + w2 * h4.z + w3 * h4.w;
        }
    }

    float bias = dir ? b_b[j] : b_f[j];
    size_t base = ((size_t)dir * TT + s) * (BB * H4);
#pragma unroll
    for (int r = 0; r < 8; r++) {
        int b = b0 + th * 8 + r;
        g_xp[base + (size_t)b * H4 + j] = acc[r] + bias;
    }
}

// ---------------- kernel 3: persistent BiLSTM ----------------
// grid (64, 2), 256 threads, 139264 B dynamic smem. CTA: 8 batch rows x 128 gate cols.
__global__ void __launch_bounds__(256, 1) lstm_kernel() {
    extern __shared__ float sm[];
    float* ws = sm;              // [256][128] weight slice (k-major)
    float* hs = sm + 32768;      // [8][256] current h tile

    int dir = blockIdx.y;
    int cta = blockIdx.x;
    int bt = cta >> 3;           // 8 batch tiles of 8
    int jt = cta & 7;            // 8 col tiles of 128
    int b_base = bt * 8;
    int tid = threadIdx.x;
    int jl = tid & 127;
    int th = tid >> 7;           // 0/1 -> rows th*4 .. th*4+3
    int j = jt * 128 + jl;

    const float* __restrict__ whh_t = g_wt[2 + dir];
    // stage weight slice into shared once (coalesced)
    for (int i = tid; i < 32768; i += 256) {
        int k = i >> 7, jj = i & 127;
        ws[i] = whh_t[k * H4 + jt * 128 + jj];
    }
    // zero h, c (each CTA owns 256 contiguous elements)
    {
        int idx = cta * 256 + tid;
        g_h[dir][idx] = 0.0f;
        g_c[dir][idx] = 0.0f;
    }
    grid_bar(dir, 64);

    for (int s = 0; s < TT; s++) {
        // load h tile [8][256]
        for (int i = tid; i < 2048; i += 256) hs[i] = g_h[dir][b_base * EE + i];
        __syncthreads();

        float acc[4];
#pragma unroll
        for (int r = 0; r < 4; r++) acc[r] = 0.0f;

#pragma unroll 4
        for (int k = 0; k < EE; k += 4) {
            float w0 = ws[(k + 0) * 128 + jl];
            float w1 = ws[(k + 1) * 128 + jl];
            float w2 = ws[(k + 2) * 128 + jl];
            float w3 = ws[(k + 3) * 128 + jl];
#pragma unroll
            for (int r = 0; r < 4; r++) {
                float4 h4 = *(const float4*)&hs[(th * 4 + r) * EE + k];
                acc[r] += w0 * h4.x + w1 * h4.y + w2 * h4.z + w3 * h4.w;
            }
        }

        const float* __restrict__ xpp = g_xp + ((size_t)dir * TT + s) * (BB * H4);
#pragma unroll
        for (int r = 0; r < 4; r++) {
            int b = b_base + th * 4 + r;
            g_gates[dir][b * H4 + j] = acc[r] + xpp[(size_t)b * H4 + j];
        }
        grid_bar(dir, 64);

        // elementwise update: each CTA owns 256 (b,e) elements
        {
            int idx = cta * 256 + tid;         // 0..16383
            int b = idx >> 8, e = idx & 255;
            const float* gg = g_gates[dir];
            float iv = sigmoidf_(gg[b * H4 + e]);
            float fv = sigmoidf_(gg[b * H4 + 256 + e]);
            float gv = tanhf(gg[b * H4 + 512 + e]);
            float ov = sigmoidf_(gg[b * H4 + 768 + e]);
            float c = fv * g_c[dir][idx] + iv * gv;
            g_c[dir][idx] = c;
            float h = ov * tanhf(c);
            g_h[dir][idx] = h;
            int t_out = dir ? (TT - 1 - s) : s;
            g_seq[((size_t)b * TT + t_out) * 512 + dir * 256 + e] = h;
        }
        grid_bar(dir, 64);
    }
}

// ---------------- kernel 4: LayerNorm + classifier + argmax ----------------
// grid 32768 (one token per block), 128 threads
__global__ void ln_logits_kernel(const float* __restrict__ gamma, const float* __restrict__ beta,
                                 const float* __restrict__ cls_w, const float* __restrict__ cls_b,
                                 float* __restrict__ out, int out_size) {
    int tok = blockIdx.x;
    int tid = threadIdx.x;
    int lane = tid & 31;
    int warp = tid >> 5;

    float4 v = ((const float4*)(g_seq + (size_t)tok * 512))[tid];
    float s1 = v.x + v.y + v.z + v.w;
    float s2 = v.x * v.x + v.y * v.y + v.z * v.z + v.w * v.w;
#pragma unroll
    for (int off = 16; off; off >>= 1) {
        s1 += __shfl_down_sync(0xffffffffu, s1, off);
        s2 += __shfl_down_sync(0xffffffffu, s2, off);
    }
    __shared__ float a1[4], a2[4];
    __shared__ float mu_s, rstd_s;
    if (lane == 0) { a1[warp] = s1; a2[warp] = s2; }
    __syncthreads();
    if (tid == 0) {
        float t1 = a1[0] + a1[1] + a1[2] + a1[3];
        float t2 = a2[0] + a2[1] + a2[2] + a2[3];
        float mu = t1 * (1.0f / 512.0f);
        float var = t2 * (1.0f / 512.0f) - mu * mu;
        mu_s = mu;
        rstd_s = rsqrtf(var + 1e-5f);
    }
    __syncthreads();
    float mu = mu_s, rstd = rstd_s;

    float4 gm = ((const float4*)gamma)[tid];
    float4 bt = ((const float4*)beta)[tid];
    float4 y;
    y.x = (v.x - mu) * rstd * gm.x + bt.x;
    y.y = (v.y - mu) * rstd * gm.y + bt.y;
    y.z = (v.z - mu) * rstd * gm.z + bt.z;
    y.w = (v.w - mu) * rstd * gm.w + bt.w;

    float p[KK];
#pragma unroll
    for (int k = 0; k < KK; k++) {
        float4 w = ((const float4*)(cls_w + k * 512))[tid];
        p[k] = y.x * w.x + y.y * w.y + y.z * w.z + y.w * w.w;
    }
#pragma unroll
    for (int off = 16; off; off >>= 1) {
#pragma unroll
        for (int k = 0; k < KK; k++) p[k] += __shfl_down_sync(0xffffffffu, p[k], off);
    }
    __shared__ float wp[4][KK];
    __shared__ float lg[KK];
    if (lane == 0) {
#pragma unroll
        for (int k = 0; k < KK; k++) wp[warp][k] = p[k];
    }
    __syncthreads();
    if (tid < KK) {
        float l = wp[0][tid] + wp[1][tid] + wp[2][tid] + wp[3][tid] + cls_b[tid];
        g_logits[tok * KK + tid] = l;
        lg[tid] = l;
    }
    __syncthreads();
    if (tid == 0) {
        int am = 0;
        float bv = lg[0];
#pragma unroll
        for (int k = 1; k < KK; k++) { if (lg[k] > bv) { bv = lg[k]; am = k; } }
        if (1 + tok < out_size) out[1 + tok] = (float)am;
    }
}

// ---------------- kernel 5: CRF (numerator + forward DP), one warp per batch ----------------
__global__ void crf_kernel(const int* __restrict__ label_ids, const float* __restrict__ crf_start,
                           const float* __restrict__ crf_end, const float* __restrict__ crf_trans) {
    int b = blockIdx.x;
    int lane = threadIdx.x;
    const unsigned FULL = 0xffffffffu;

    // numerator (parallel over t, strided by lanes)
    float num = 0.0f;
    for (int t = lane; t < TT; t += 32) {
        int tg = label_ids[b * TT + t];
        num += g_logits[(b * TT + t) * KK + tg];
        if (t < TT - 1) num += crf_trans[tg * KK + label_ids[b * TT + t + 1]];
    }
#pragma unroll
    for (int off = 16; off; off >>= 1) num += __shfl_down_sync(FULL, num, off);
    if (lane == 0) {
        num += crf_start[label_ids[b * TT]] + crf_end[label_ids[b * TT + TT - 1]];
    }

    // forward DP: lane j (<9) holds alpha[j]
    bool act = lane < KK;
    float tcol[KK];
#pragma unroll
    for (int k = 0; k < KK; k++) tcol[k] = act ? crf_trans[k * KK + lane] : 0.0f;
    float alpha = act ? (crf_start[lane] + g_logits[(size_t)b * TT * KK + lane]) : -1e30f;

    for (int t = 1; t < TT; t++) {
        float em = act ? g_logits[((size_t)b * TT + t) * KK + lane] : 0.0f;
        float va[KK];
#pragma unroll
        for (int k = 0; k < KK; k++) va[k] = __shfl_sync(FULL, alpha, k) + tcol[k];
        float m = va[0];
#pragma unroll
        for (int k = 1; k < KK; k++) m = fmaxf(m, va[k]);
        float sme = 0.0f;
#pragma unroll
        for (int k = 0; k < KK; k++) sme += expf(va[k] - m);
        float na = em + m + logf(sme);
        alpha = act ? na : -1e30f;
    }

    // logZ = lse(alpha + end)
    float v = act ? (alpha + crf_end[lane]) : -1e30f;
    float m = v;
#pragma unroll
    for (int off = 16; off; off >>= 1) m = fmaxf(m, __shfl_xor_sync(FULL, m, off));
    float e = expf(v - m);
#pragma unroll
    for (int off = 16; off; off >>= 1) e += __shfl_xor_sync(FULL, e, off);
    float logZ = m + logf(e);

    if (lane == 0) g_llh[b] = num - logZ;
}

// ---------------- kernel 6: final loss reduction ----------------
__global__ void loss_kernel(float* __restrict__ out) {
    __shared__ float s[BB];
    int tid = threadIdx.x;
    s[tid] = g_llh[tid];
    __syncthreads();
    for (int off = 32; off; off >>= 1) {
        if (tid < off) s[tid] += s[tid + off];
        __syncthreads();
    }
    if (tid == 0) out[0] = -s[0];
}

// ---------------- launch ----------------
extern "C" void kernel_launch(void* const* d_in, const int* in_sizes, int n_in,
                              void* d_out, int out_size) {
    const int*   word_ids  = (const int*)d_in[0];
    const int*   label_ids = (const int*)d_in[1];
    const float* embed     = (const float*)d_in[2];
    const float* w_ih_f    = (const float*)d_in[3];
    const float* w_hh_f    = (const float*)d_in[4];
    const float* b_f       = (const float*)d_in[5];
    const float* w_ih_b    = (const float*)d_in[6];
    const float* w_hh_b    = (const float*)d_in[7];
    const float* b_b       = (const float*)d_in[8];
    const float* ln_gamma  = (const float*)d_in[9];
    const float* ln_beta   = (const float*)d_in[10];
    const float* cls_w     = (const float*)d_in[11];
    const float* cls_b     = (const float*)d_in[12];
    const float* crf_start = (const float*)d_in[13];
    const float* crf_end   = (const float*)d_in[14];
    const float* crf_trans = (const float*)d_in[15];
    float* out = (float*)d_out;

    const int LSTM_SMEM = (32768 + 2048) * 4;   // 139264 B
    cudaFuncSetAttribute(lstm_kernel, cudaFuncAttributeMaxDynamicSharedMemorySize, LSTM_SMEM);

    transpose_w_kernel<<<4096, 256>>>(w_ih_f, w_ih_b, w_hh_f, w_hh_b);
    proj_kernel<<<dim3(2048, 8, 2), 256>>>(word_ids, embed, b_f, b_b);
    lstm_kernel<<<dim3(64, 2), 256, LSTM_SMEM>>>();
    ln_logits_kernel<<<32768, 128>>>(ln_gamma, ln_beta, cls_w, cls_b, out, out_size);
    crf_kernel<<<BB, 32>>>(label_ids, crf_start, crf_end, crf_trans);
    loss_kernel<<<1, BB>>>(out);
}